// round 1
// baseline (speedup 1.0000x reference)
#include <cuda_runtime.h>

#define BB 2
#define SS 2048
#define DD 1024
#define HH 16
#define HD 64

// Head-major scratch [b, h, s, c] — allocation-free per harness rules.
__device__ float g_Q[BB * HH * SS * HD];
__device__ float g_K[BB * HH * SS * HD];
__device__ float g_V[BB * HH * SS * HD];

// ---------------------------------------------------------------------------
// QKV projection GEMM: C[n, col] = sum_d X[n, d] * W[d, col]
// Tile 64x64, BK=16, 256 threads, 4x4 register microtile.
// Output scattered to head-major [b, h, s, c].
// ---------------------------------------------------------------------------
__global__ __launch_bounds__(256) void qkv_gemm_kernel(
    const float* __restrict__ X, const float* __restrict__ W, int which)
{
    __shared__ float Xs[16][68];   // [k][row], padded for float4-aligned rows
    __shared__ float Ws[16][68];   // [k][col]

    float* Out = (which == 0) ? g_Q : ((which == 1) ? g_K : g_V);

    const int tid = threadIdx.x;
    const int tx = tid & 15, ty = tid >> 4;
    const int n0 = blockIdx.y * 64;
    const int j0 = blockIdx.x * 64;

    // load assignments
    const int lrow = tid >> 2;            // 0..63  X row within tile
    const int lkq  = (tid & 3) * 4;       // k offset of float4
    const int wkk  = tid >> 4;            // 0..15  W row within tile
    const int wjq  = (tid & 15) * 4;      // col offset of float4

    float acc[4][4] = {};

    for (int k0 = 0; k0 < DD; k0 += 16) {
        float4 xv = *(const float4*)&X[(n0 + lrow) * DD + k0 + lkq];
        float4 wv = *(const float4*)&W[(k0 + wkk) * DD + j0 + wjq];
        Xs[lkq + 0][lrow] = xv.x;
        Xs[lkq + 1][lrow] = xv.y;
        Xs[lkq + 2][lrow] = xv.z;
        Xs[lkq + 3][lrow] = xv.w;
        *(float4*)&Ws[wkk][wjq] = wv;
        __syncthreads();

#pragma unroll
        for (int kk = 0; kk < 16; kk++) {
            float4 a = *(float4*)&Xs[kk][ty * 4];
            float4 b = *(float4*)&Ws[kk][tx * 4];
            float av[4] = {a.x, a.y, a.z, a.w};
            float bv[4] = {b.x, b.y, b.z, b.w};
#pragma unroll
            for (int i = 0; i < 4; i++)
#pragma unroll
                for (int j = 0; j < 4; j++)
                    acc[i][j] += av[i] * bv[j];
        }
        __syncthreads();
    }

#pragma unroll
    for (int i = 0; i < 4; i++) {
        int n = n0 + ty * 4 + i;
        int b = n >> 11, s = n & (SS - 1);
#pragma unroll
        for (int j = 0; j < 4; j++) {
            int col = j0 + tx * 4 + j;
            int h = col >> 6, c = col & 63;
            Out[((b * HH + h) * SS + s) * HD + c] = acc[i][j];
        }
    }
}

// ---------------------------------------------------------------------------
// Flash attention: per block = one (b,h) pair, 64 query rows.
// BK=32 K/V tiles, online softmax, 256 threads (16x16 grid).
// Score phase: 4 rows x 2 cols per thread.  PV phase: 4 rows x 4 cols.
// ---------------------------------------------------------------------------
__global__ __launch_bounds__(256) void flash_attn_kernel(
    const float* __restrict__ mask, float* __restrict__ out)
{
    __shared__ float Qs[64][68];   // [row][k]
    __shared__ float Kts[64][36];  // [k][j]  (K transposed)
    __shared__ float Vs[32][68];   // [j][c]
    __shared__ float Ps[64][34];   // [row][j] softmaxed probabilities

    const int tid = threadIdx.x;
    const int tx = tid & 15, ty = tid >> 4;
    const int q0 = blockIdx.x * 64;
    const int bh = blockIdx.y;
    const int b = bh >> 4, h = bh & 15;

    const float* Qb = g_Q + (size_t)bh * SS * HD;
    const float* Kb = g_K + (size_t)bh * SS * HD;
    const float* Vb = g_V + (size_t)bh * SS * HD;
    const float* maskb = mask + b * SS;

    // load the Q tile once
#pragma unroll
    for (int u = 0; u < 4; u++) {
        int id = u * 256 + tid;
        int r = id >> 4;
        int kq = (id & 15) * 4;
        *(float4*)&Qs[r][kq] = *(const float4*)&Qb[(q0 + r) * HD + kq];
    }

    float m_[4], l_[4], o_[4][4];
#pragma unroll
    for (int i = 0; i < 4; i++) {
        m_[i] = -1e30f;
        l_[i] = 0.f;
#pragma unroll
        for (int j = 0; j < 4; j++) o_[i][j] = 0.f;
    }

    for (int kt = 0; kt < SS; kt += 32) {
        __syncthreads();  // protect smem from previous iteration's readers
        // load K (transposed) and V tiles
#pragma unroll
        for (int u = 0; u < 2; u++) {
            int id = u * 256 + tid;
            int j = id >> 4;
            int kq = (id & 15) * 4;
            float4 kv = *(const float4*)&Kb[(kt + j) * HD + kq];
            Kts[kq + 0][j] = kv.x;
            Kts[kq + 1][j] = kv.y;
            Kts[kq + 2][j] = kv.z;
            Kts[kq + 3][j] = kv.w;
            *(float4*)&Vs[j][kq] = *(const float4*)&Vb[(kt + j) * HD + kq];
        }
        float mv0 = maskb[kt + tx * 2 + 0] * -1e9f;
        float mv1 = maskb[kt + tx * 2 + 1] * -1e9f;
        __syncthreads();

        // ---- scores: S[64x32] = Q * K^T ----
        float s0[4] = {0.f, 0.f, 0.f, 0.f};
        float s1[4] = {0.f, 0.f, 0.f, 0.f};
#pragma unroll 8
        for (int k = 0; k < 64; k++) {
            float b0 = Kts[k][tx * 2 + 0];
            float b1 = Kts[k][tx * 2 + 1];
#pragma unroll
            for (int i = 0; i < 4; i++) {
                float a = Qs[ty * 4 + i][k];
                s0[i] += a * b0;
                s1[i] += a * b1;
            }
        }

        // ---- online softmax update ----
#pragma unroll
        for (int i = 0; i < 4; i++) {
            float v0 = s0[i] * 0.125f + mv0;   // /sqrt(64) + additive mask
            float v1 = s1[i] * 0.125f + mv1;
            float mx = fmaxf(v0, v1);
#pragma unroll
            for (int off = 8; off >= 1; off >>= 1)
                mx = fmaxf(mx, __shfl_xor_sync(0xffffffffu, mx, off));
            float mnew = fmaxf(m_[i], mx);
            float alpha = __expf(m_[i] - mnew);
            m_[i] = mnew;
            float p0 = __expf(v0 - mnew);
            float p1 = __expf(v1 - mnew);
            Ps[ty * 4 + i][tx * 2 + 0] = p0;
            Ps[ty * 4 + i][tx * 2 + 1] = p1;
            float rs = p0 + p1;
#pragma unroll
            for (int off = 8; off >= 1; off >>= 1)
                rs += __shfl_xor_sync(0xffffffffu, rs, off);
            l_[i] = l_[i] * alpha + rs;
#pragma unroll
            for (int j = 0; j < 4; j++) o_[i][j] *= alpha;
        }
        __syncthreads();

        // ---- O += P * V ----
#pragma unroll 8
        for (int jj = 0; jj < 32; jj++) {
            float4 vv = *(float4*)&Vs[jj][tx * 4];
#pragma unroll
            for (int i = 0; i < 4; i++) {
                float p = Ps[ty * 4 + i][jj];
                o_[i][0] += p * vv.x;
                o_[i][1] += p * vv.y;
                o_[i][2] += p * vv.z;
                o_[i][3] += p * vv.w;
            }
        }
    }

    // epilogue: normalize and write [b, s, h*64 + c]
#pragma unroll
    for (int i = 0; i < 4; i++) {
        float inv = 1.0f / l_[i];
        int srow = q0 + ty * 4 + i;
        float4 ov = make_float4(o_[i][0] * inv, o_[i][1] * inv,
                                o_[i][2] * inv, o_[i][3] * inv);
        *(float4*)&out[(size_t)(b * SS + srow) * DD + h * HD + tx * 4] = ov;
    }
}

// ---------------------------------------------------------------------------
extern "C" void kernel_launch(void* const* d_in, const int* in_sizes, int n_in,
                              void* d_out, int out_size)
{
    const float* X    = (const float*)d_in[0];
    const float* mask = (const float*)d_in[1];
    const float* wq   = (const float*)d_in[2];
    const float* wk   = (const float*)d_in[3];
    const float* wv   = (const float*)d_in[4];
    float* out = (float*)d_out;

    dim3 gg(DD / 64, (BB * SS) / 64);  // (16, 64)
    qkv_gemm_kernel<<<gg, 256>>>(X, wq, 0);
    qkv_gemm_kernel<<<gg, 256>>>(X, wk, 1);
    qkv_gemm_kernel<<<gg, 256>>>(X, wv, 2);

    dim3 ga(SS / 64, BB * HH);         // (32, 32)
    flash_attn_kernel<<<ga, 256>>>(mask, out);
}

// round 3
// speedup vs baseline: 1.2724x; 1.2724x over previous
#include <cuda_runtime.h>
#include <cuda_bf16.h>
#include <cstdint>

#define BB 2
#define SS 2048
#define DD 1024
#define HH 16
#define HD 64

// ---------------------------------------------------------------------------
// Global scratch (allocation-free per harness rules)
// ---------------------------------------------------------------------------
__device__ float g_Q[BB * HH * SS * HD];
__device__ float g_K[BB * HH * SS * HD];
__device__ float g_V[BB * HH * SS * HD];

__device__ __nv_bfloat16 g_Xhi[BB * SS * DD];
__device__ __nv_bfloat16 g_Xlo[BB * SS * DD];
__device__ __nv_bfloat16 g_Whi[3 * DD * DD];   // transposed: [mat][n][k]
__device__ __nv_bfloat16 g_Wlo[3 * DD * DD];

// ---------------------------------------------------------------------------
// Warp-MMA helpers (sm_80-class instructions — valid on compute_100)
// ---------------------------------------------------------------------------
__device__ __forceinline__ uint32_t smem_u32(const void* p) {
    uint32_t a;
    asm("{ .reg .u64 t; cvta.to.shared.u64 t, %1; cvt.u32.u64 %0, t; }" : "=r"(a) : "l"(p));
    return a;
}

__device__ __forceinline__ void ldm_x4(uint32_t* r, uint32_t addr) {
    asm volatile("ldmatrix.sync.aligned.m8n8.x4.shared.b16 {%0,%1,%2,%3}, [%4];"
                 : "=r"(r[0]), "=r"(r[1]), "=r"(r[2]), "=r"(r[3]) : "r"(addr));
}

__device__ __forceinline__ void mma16816(float* c, const uint32_t* a, uint32_t b0, uint32_t b1) {
    asm volatile(
        "mma.sync.aligned.m16n8k16.row.col.f32.bf16.bf16.f32 "
        "{%0,%1,%2,%3}, {%4,%5,%6,%7}, {%8,%9}, {%0,%1,%2,%3};"
        : "+f"(c[0]), "+f"(c[1]), "+f"(c[2]), "+f"(c[3])
        : "r"(a[0]), "r"(a[1]), "r"(a[2]), "r"(a[3]), "r"(b0), "r"(b1));
}

// ---------------------------------------------------------------------------
// Prep: split X into bf16 hi/lo
// ---------------------------------------------------------------------------
__global__ __launch_bounds__(256) void convert_x_kernel(const float* __restrict__ X)
{
    int idx = blockIdx.x * 256 + threadIdx.x;          // float4 index
    float4 v = ((const float4*)X)[idx];
    float f[4] = {v.x, v.y, v.z, v.w};
    __nv_bfloat16 h[4], l[4];
#pragma unroll
    for (int i = 0; i < 4; i++) {
        h[i] = __float2bfloat16(f[i]);
        l[i] = __float2bfloat16(f[i] - __bfloat162float(h[i]));
    }
    __nv_bfloat162* dh = (__nv_bfloat162*)g_Xhi;
    __nv_bfloat162* dl = (__nv_bfloat162*)g_Xlo;
    dh[idx * 2 + 0] = __nv_bfloat162(h[0], h[1]);
    dh[idx * 2 + 1] = __nv_bfloat162(h[2], h[3]);
    dl[idx * 2 + 0] = __nv_bfloat162(l[0], l[1]);
    dl[idx * 2 + 1] = __nv_bfloat162(l[2], l[3]);
}

// ---------------------------------------------------------------------------
// Prep: transpose W [k][n] -> Wt [n][k] and split into bf16 hi/lo
// ---------------------------------------------------------------------------
__global__ __launch_bounds__(256) void convert_w_kernel(
    const float* __restrict__ wq, const float* __restrict__ wk, const float* __restrict__ wv)
{
    __shared__ float t[32][33];
    const int z = blockIdx.z;
    const float* W = (z == 0) ? wq : ((z == 1) ? wk : wv);
    const int tx = threadIdx.x, ty = threadIdx.y;
    const int n_in = blockIdx.x * 32 + tx;
#pragma unroll
    for (int j = 0; j < 4; j++) {
        int k = blockIdx.y * 32 + ty + j * 8;
        t[ty + j * 8][tx] = W[k * DD + n_in];
    }
    __syncthreads();
#pragma unroll
    for (int j = 0; j < 4; j++) {
        int n = blockIdx.x * 32 + ty + j * 8;
        int k = blockIdx.y * 32 + tx;
        float v = t[tx][ty + j * 8];
        __nv_bfloat16 h = __float2bfloat16(v);
        __nv_bfloat16 l = __float2bfloat16(v - __bfloat162float(h));
        size_t o = (size_t)z * DD * DD + (size_t)n * DD + k;
        g_Whi[o] = h;
        g_Wlo[o] = l;
    }
}

// ---------------------------------------------------------------------------
// mma.sync QKV GEMM: C[4096 x 1024] = X @ W, split-bf16 (3 MMAs per atom),
// fp32 accumulators. Tile 128x128, BK=32, 8 warps (2x4), warp tile 64x32.
// Epilogue scatters fp32 into head-major g_Q/g_K/g_V.
// ---------------------------------------------------------------------------
#define RS 40                    // smem row stride in bf16 elems (80 B)
#define RSB 80                   // row stride bytes

__global__ __launch_bounds__(256) void qkv_mma_kernel()
{
    __shared__ __align__(16) __nv_bfloat16 sAh[128 * RS];
    __shared__ __align__(16) __nv_bfloat16 sAl[128 * RS];
    __shared__ __align__(16) __nv_bfloat16 sBh[128 * RS];
    __shared__ __align__(16) __nv_bfloat16 sBl[128 * RS];

    const int tid  = threadIdx.x;
    const int warp = tid >> 5, lane = tid & 31;
    const int warp_m = (warp & 1) * 64;     // token-dim offset within tile
    const int warp_n = (warp >> 1) * 32;    // col-dim offset within tile
    const int j0 = blockIdx.x * 128;        // output cols
    const int n0 = blockIdx.y * 128;        // token rows
    const int z  = blockIdx.z;              // 0=Q 1=K 2=V

    const char* Ahp = (const char*)g_Xhi + (size_t)n0 * (DD * 2);
    const char* Alp = (const char*)g_Xlo + (size_t)n0 * (DD * 2);
    const char* Bhp = (const char*)g_Whi + ((size_t)z * DD * DD + (size_t)j0 * DD) * 2;
    const char* Blp = (const char*)g_Wlo + ((size_t)z * DD * DD + (size_t)j0 * DD) * 2;

    const uint32_t uAh = smem_u32(sAh), uAl = smem_u32(sAl);
    const uint32_t uBh = smem_u32(sBh), uBl = smem_u32(sBl);

    float acc[4][4][4] = {};                // [m-atom][n-atom][frag]

    // per-thread ldmatrix address components
    const uint32_t a_row = warp_m + (lane & 15);        // A: rows 0..15 per atom
    const uint32_t a_col = (lane >> 4) * 16;            // k-half byte offset
    const uint32_t b_row = warp_n + (lane & 7) + ((lane >> 3) & 1) * 8;  // B: n 0..15
    const uint32_t b_col = (lane >> 4) * 16;

    for (int kc = 0; kc < 32; kc++) {
        __syncthreads();                    // previous chunk fully consumed
        const size_t kb = (size_t)kc * 64;  // byte offset of k-chunk within row
#pragma unroll
        for (int u = 0; u < 2; u++) {
            int id = u * 256 + tid;         // 512 uint4 per tile
            int row = id >> 2;
            int qb  = (id & 3) * 16;
            size_t go = (size_t)row * (DD * 2) + kb + qb;
            uint32_t so = row * RSB + qb;
            *(uint4*)((char*)sAh + so) = *(const uint4*)(Ahp + go);
            *(uint4*)((char*)sAl + so) = *(const uint4*)(Alp + go);
            *(uint4*)((char*)sBh + so) = *(const uint4*)(Bhp + go);
            *(uint4*)((char*)sBl + so) = *(const uint4*)(Blp + go);
        }
        __syncthreads();

#pragma unroll
        for (int ks = 0; ks < 2; ks++) {
            const uint32_t koff = ks * 32;  // 16 bf16 = 32 B
            uint32_t ah[4][4], al[4][4];
#pragma unroll
            for (int i = 0; i < 4; i++) {
                uint32_t off = (a_row + i * 16) * RSB + koff + a_col;
                ldm_x4(ah[i], uAh + off);
                ldm_x4(al[i], uAl + off);
            }
            uint32_t bh[2][4], bl[2][4];
#pragma unroll
            for (int p = 0; p < 2; p++) {
                uint32_t off = (b_row + p * 16) * RSB + koff + b_col;
                ldm_x4(bh[p], uBh + off);
                ldm_x4(bl[p], uBl + off);
            }
#pragma unroll
            for (int i = 0; i < 4; i++) {
#pragma unroll
                for (int j = 0; j < 4; j++) {
                    const int p = j >> 1, q = j & 1;
                    mma16816(acc[i][j], ah[i], bh[p][q], bh[p][q + 2]);   // hi*hi
                    mma16816(acc[i][j], ah[i], bl[p][q], bl[p][q + 2]);   // hi*lo
                    mma16816(acc[i][j], al[i], bh[p][q], bh[p][q + 2]);   // lo*hi
                }
            }
        }
    }

    // Epilogue: fragments -> head-major [b, h, s, c]
    float* Out = (z == 0) ? g_Q : ((z == 1) ? g_K : g_V);
    const int r_base = lane >> 2;
    const int c_base = (lane & 3) * 2;
#pragma unroll
    for (int i = 0; i < 4; i++) {
#pragma unroll
        for (int j = 0; j < 4; j++) {
            int col = j0 + warp_n + j * 8 + c_base;
            int h = col >> 6, c = col & 63;
            int n1 = n0 + warp_m + i * 16 + r_base;
            int b1 = n1 >> 11, s1 = n1 & (SS - 1);
            *(float2*)&Out[(((size_t)(b1 * HH + h) * SS + s1) * HD) + c] =
                make_float2(acc[i][j][0], acc[i][j][1]);
            int n2 = n1 + 8;
            int b2 = n2 >> 11, s2 = n2 & (SS - 1);
            *(float2*)&Out[(((size_t)(b2 * HH + h) * SS + s2) * HD) + c] =
                make_float2(acc[i][j][2], acc[i][j][3]);
        }
    }
}

// ---------------------------------------------------------------------------
// Flash attention (unchanged — known good)
// ---------------------------------------------------------------------------
__global__ __launch_bounds__(256) void flash_attn_kernel(
    const float* __restrict__ mask, float* __restrict__ out)
{
    __shared__ float Qs[64][68];
    __shared__ float Kts[64][36];
    __shared__ float Vs[32][68];
    __shared__ float Ps[64][34];

    const int tid = threadIdx.x;
    const int tx = tid & 15, ty = tid >> 4;
    const int q0 = blockIdx.x * 64;
    const int bh = blockIdx.y;
    const int b = bh >> 4, h = bh & 15;

    const float* Qb = g_Q + (size_t)bh * SS * HD;
    const float* Kb = g_K + (size_t)bh * SS * HD;
    const float* Vb = g_V + (size_t)bh * SS * HD;
    const float* maskb = mask + b * SS;

#pragma unroll
    for (int u = 0; u < 4; u++) {
        int id = u * 256 + tid;
        int r = id >> 4;
        int kq = (id & 15) * 4;
        *(float4*)&Qs[r][kq] = *(const float4*)&Qb[(q0 + r) * HD + kq];
    }

    float m_[4], l_[4], o_[4][4];
#pragma unroll
    for (int i = 0; i < 4; i++) {
        m_[i] = -1e30f;
        l_[i] = 0.f;
#pragma unroll
        for (int j = 0; j < 4; j++) o_[i][j] = 0.f;
    }

    for (int kt = 0; kt < SS; kt += 32) {
        __syncthreads();
#pragma unroll
        for (int u = 0; u < 2; u++) {
            int id = u * 256 + tid;
            int j = id >> 4;
            int kq = (id & 15) * 4;
            float4 kv = *(const float4*)&Kb[(kt + j) * HD + kq];
            Kts[kq + 0][j] = kv.x;
            Kts[kq + 1][j] = kv.y;
            Kts[kq + 2][j] = kv.z;
            Kts[kq + 3][j] = kv.w;
            *(float4*)&Vs[j][kq] = *(const float4*)&Vb[(kt + j) * HD + kq];
        }
        float mv0 = maskb[kt + tx * 2 + 0] * -1e9f;
        float mv1 = maskb[kt + tx * 2 + 1] * -1e9f;
        __syncthreads();

        float s0[4] = {0.f, 0.f, 0.f, 0.f};
        float s1[4] = {0.f, 0.f, 0.f, 0.f};
#pragma unroll 8
        for (int k = 0; k < 64; k++) {
            float b0 = Kts[k][tx * 2 + 0];
            float b1 = Kts[k][tx * 2 + 1];
#pragma unroll
            for (int i = 0; i < 4; i++) {
                float a = Qs[ty * 4 + i][k];
                s0[i] += a * b0;
                s1[i] += a * b1;
            }
        }

#pragma unroll
        for (int i = 0; i < 4; i++) {
            float v0 = s0[i] * 0.125f + mv0;
            float v1 = s1[i] * 0.125f + mv1;
            float mx = fmaxf(v0, v1);
#pragma unroll
            for (int off = 8; off >= 1; off >>= 1)
                mx = fmaxf(mx, __shfl_xor_sync(0xffffffffu, mx, off));
            float mnew = fmaxf(m_[i], mx);
            float alpha = __expf(m_[i] - mnew);
            m_[i] = mnew;
            float p0 = __expf(v0 - mnew);
            float p1 = __expf(v1 - mnew);
            Ps[ty * 4 + i][tx * 2 + 0] = p0;
            Ps[ty * 4 + i][tx * 2 + 1] = p1;
            float rs = p0 + p1;
#pragma unroll
            for (int off = 8; off >= 1; off >>= 1)
                rs += __shfl_xor_sync(0xffffffffu, rs, off);
            l_[i] = l_[i] * alpha + rs;
#pragma unroll
            for (int j = 0; j < 4; j++) o_[i][j] *= alpha;
        }
        __syncthreads();

#pragma unroll 8
        for (int jj = 0; jj < 32; jj++) {
            float4 vv = *(float4*)&Vs[jj][tx * 4];
#pragma unroll
            for (int i = 0; i < 4; i++) {
                float p = Ps[ty * 4 + i][jj];
                o_[i][0] += p * vv.x;
                o_[i][1] += p * vv.y;
                o_[i][2] += p * vv.z;
                o_[i][3] += p * vv.w;
            }
        }
    }

#pragma unroll
    for (int i = 0; i < 4; i++) {
        float inv = 1.0f / l_[i];
        int srow = q0 + ty * 4 + i;
        float4 ov = make_float4(o_[i][0] * inv, o_[i][1] * inv,
                                o_[i][2] * inv, o_[i][3] * inv);
        *(float4*)&out[(size_t)(b * SS + srow) * DD + h * HD + tx * 4] = ov;
    }
}

// ---------------------------------------------------------------------------
extern "C" void kernel_launch(void* const* d_in, const int* in_sizes, int n_in,
                              void* d_out, int out_size)
{
    const float* X    = (const float*)d_in[0];
    const float* mask = (const float*)d_in[1];
    const float* wq   = (const float*)d_in[2];
    const float* wk   = (const float*)d_in[3];
    const float* wv   = (const float*)d_in[4];
    float* out = (float*)d_out;

    convert_x_kernel<<<(BB * SS * DD) / 4 / 256, 256>>>(X);
    convert_w_kernel<<<dim3(DD / 32, DD / 32, 3), dim3(32, 8)>>>(wq, wk, wv);
    qkv_mma_kernel<<<dim3(DD / 128, (BB * SS) / 128, 3), 256>>>();

    dim3 ga(SS / 64, BB * HH);
    flash_attn_kernel<<<ga, 256>>>(mask, out);
}

// round 7
// speedup vs baseline: 2.4386x; 1.9166x over previous
#include <cuda_runtime.h>
#include <cuda_bf16.h>
#include <cstdint>

#define BB 2
#define SS 2048
#define DD 1024
#define HH 16
#define HD 64

// ---------------------------------------------------------------------------
// Global scratch (allocation-free per harness rules)
// ---------------------------------------------------------------------------
__device__ float g_V[BB * HH * SS * HD];                 // fp32 V (transpose source)

__device__ __nv_bfloat16 g_Qhi[BB * HH * SS * HD];
__device__ __nv_bfloat16 g_Qlo[BB * HH * SS * HD];
__device__ __nv_bfloat16 g_Khi[BB * HH * SS * HD];
__device__ __nv_bfloat16 g_Klo[BB * HH * SS * HD];
__device__ __nv_bfloat16 g_Vthi[BB * HH * HD * SS];      // [bh][c][s]
__device__ __nv_bfloat16 g_Vtlo[BB * HH * HD * SS];

__device__ __nv_bfloat16 g_Xhi[BB * SS * DD];
__device__ __nv_bfloat16 g_Xlo[BB * SS * DD];
__device__ __nv_bfloat16 g_Whi[3 * DD * DD];             // transposed: [mat][n][k]
__device__ __nv_bfloat16 g_Wlo[3 * DD * DD];

// ---------------------------------------------------------------------------
// Warp-MMA helpers
// ---------------------------------------------------------------------------
__device__ __forceinline__ uint32_t smem_u32(const void* p) {
    uint32_t a;
    asm("{ .reg .u64 t; cvta.to.shared.u64 t, %1; cvt.u32.u64 %0, t; }" : "=r"(a) : "l"(p));
    return a;
}
__device__ __forceinline__ void ldm_x4(uint32_t* r, uint32_t addr) {
    asm volatile("ldmatrix.sync.aligned.m8n8.x4.shared.b16 {%0,%1,%2,%3}, [%4];"
                 : "=r"(r[0]), "=r"(r[1]), "=r"(r[2]), "=r"(r[3]) : "r"(addr));
}
__device__ __forceinline__ void mma16816(float* c, const uint32_t* a, uint32_t b0, uint32_t b1) {
    asm volatile(
        "mma.sync.aligned.m16n8k16.row.col.f32.bf16.bf16.f32 "
        "{%0,%1,%2,%3}, {%4,%5,%6,%7}, {%8,%9}, {%0,%1,%2,%3};"
        : "+f"(c[0]), "+f"(c[1]), "+f"(c[2]), "+f"(c[3])
        : "r"(a[0]), "r"(a[1]), "r"(a[2]), "r"(a[3]), "r"(b0), "r"(b1));
}
__device__ __forceinline__ void split_pack(float a, float b, uint32_t& hi, uint32_t& lo) {
    __nv_bfloat16 ha = __float2bfloat16(a), hb = __float2bfloat16(b);
    __nv_bfloat16 la = __float2bfloat16(a - __bfloat162float(ha));
    __nv_bfloat16 lb = __float2bfloat16(b - __bfloat162float(hb));
    __nv_bfloat162 h2(ha, hb), l2(la, lb);
    hi = *(uint32_t*)&h2;
    lo = *(uint32_t*)&l2;
}

// ---------------------------------------------------------------------------
// Prep: split X into bf16 hi/lo
// ---------------------------------------------------------------------------
__global__ __launch_bounds__(256) void convert_x_kernel(const float* __restrict__ X)
{
    int idx = blockIdx.x * 256 + threadIdx.x;
    float4 v = ((const float4*)X)[idx];
    float f[4] = {v.x, v.y, v.z, v.w};
    __nv_bfloat16 h[4], l[4];
#pragma unroll
    for (int i = 0; i < 4; i++) {
        h[i] = __float2bfloat16(f[i]);
        l[i] = __float2bfloat16(f[i] - __bfloat162float(h[i]));
    }
    __nv_bfloat162* dh = (__nv_bfloat162*)g_Xhi;
    __nv_bfloat162* dl = (__nv_bfloat162*)g_Xlo;
    dh[idx * 2 + 0] = __nv_bfloat162(h[0], h[1]);
    dh[idx * 2 + 1] = __nv_bfloat162(h[2], h[3]);
    dl[idx * 2 + 0] = __nv_bfloat162(l[0], l[1]);
    dl[idx * 2 + 1] = __nv_bfloat162(l[2], l[3]);
}

// ---------------------------------------------------------------------------
// Prep: transpose W [k][n] -> Wt [n][k], split bf16 hi/lo
// ---------------------------------------------------------------------------
__global__ __launch_bounds__(256) void convert_w_kernel(
    const float* __restrict__ wq, const float* __restrict__ wk, const float* __restrict__ wv)
{
    __shared__ float t[32][33];
    const int z = blockIdx.z;
    const float* W = (z == 0) ? wq : ((z == 1) ? wk : wv);
    const int tx = threadIdx.x, ty = threadIdx.y;
    const int n_in = blockIdx.x * 32 + tx;
#pragma unroll
    for (int j = 0; j < 4; j++) {
        int k = blockIdx.y * 32 + ty + j * 8;
        t[ty + j * 8][tx] = W[k * DD + n_in];
    }
    __syncthreads();
#pragma unroll
    for (int j = 0; j < 4; j++) {
        int n = blockIdx.x * 32 + ty + j * 8;
        int k = blockIdx.y * 32 + tx;
        float v = t[tx][ty + j * 8];
        __nv_bfloat16 h = __float2bfloat16(v);
        __nv_bfloat16 l = __float2bfloat16(v - __bfloat162float(h));
        size_t o = (size_t)z * DD * DD + (size_t)n * DD + k;
        g_Whi[o] = h;
        g_Wlo[o] = l;
    }
}

// ---------------------------------------------------------------------------
// mma.sync QKV GEMM. Q,K epilogue -> bf16 hi/lo head-major. V -> fp32.
// Rows are 32 bf16 = 64 B, stride RSB = 80 B.
// ---------------------------------------------------------------------------
#define RS 40
#define RSB 80

__global__ __launch_bounds__(256) void qkv_mma_kernel()
{
    __shared__ __align__(16) __nv_bfloat16 sAh[128 * RS];
    __shared__ __align__(16) __nv_bfloat16 sAl[128 * RS];
    __shared__ __align__(16) __nv_bfloat16 sBh[128 * RS];
    __shared__ __align__(16) __nv_bfloat16 sBl[128 * RS];

    const int tid  = threadIdx.x;
    const int warp = tid >> 5, lane = tid & 31;
    const int warp_m = (warp & 1) * 64;
    const int warp_n = (warp >> 1) * 32;
    const int j0 = blockIdx.x * 128;
    const int n0 = blockIdx.y * 128;
    const int z  = blockIdx.z;

    const char* Ahp = (const char*)g_Xhi + (size_t)n0 * (DD * 2);
    const char* Alp = (const char*)g_Xlo + (size_t)n0 * (DD * 2);
    const char* Bhp = (const char*)g_Whi + ((size_t)z * DD * DD + (size_t)j0 * DD) * 2;
    const char* Blp = (const char*)g_Wlo + ((size_t)z * DD * DD + (size_t)j0 * DD) * 2;

    const uint32_t uAh = smem_u32(sAh), uAl = smem_u32(sAl);
    const uint32_t uBh = smem_u32(sBh), uBl = smem_u32(sBl);

    float acc[4][4][4] = {};

    const uint32_t a_row = warp_m + (lane & 15);
    const uint32_t a_col = (lane >> 4) * 16;
    const uint32_t b_row = warp_n + (lane & 7) + ((lane >> 3) & 1) * 8;
    const uint32_t b_col = (lane >> 4) * 16;

    for (int kc = 0; kc < 32; kc++) {
        __syncthreads();
        const size_t kb = (size_t)kc * 64;
#pragma unroll
        for (int u = 0; u < 2; u++) {
            int id = u * 256 + tid;
            int row = id >> 2;
            int qb  = (id & 3) * 16;
            size_t go = (size_t)row * (DD * 2) + kb + qb;
            uint32_t so = row * RSB + qb;
            *(uint4*)((char*)sAh + so) = *(const uint4*)(Ahp + go);
            *(uint4*)((char*)sAl + so) = *(const uint4*)(Alp + go);
            *(uint4*)((char*)sBh + so) = *(const uint4*)(Bhp + go);
            *(uint4*)((char*)sBl + so) = *(const uint4*)(Blp + go);
        }
        __syncthreads();

#pragma unroll
        for (int ks = 0; ks < 2; ks++) {
            const uint32_t koff = ks * 32;
            uint32_t ah[4][4], al[4][4];
#pragma unroll
            for (int i = 0; i < 4; i++) {
                uint32_t off = (a_row + i * 16) * RSB + koff + a_col;
                ldm_x4(ah[i], uAh + off);
                ldm_x4(al[i], uAl + off);
            }
            uint32_t bh[2][4], bl[2][4];
#pragma unroll
            for (int p = 0; p < 2; p++) {
                uint32_t off = (b_row + p * 16) * RSB + koff + b_col;
                ldm_x4(bh[p], uBh + off);
                ldm_x4(bl[p], uBl + off);
            }
#pragma unroll
            for (int i = 0; i < 4; i++) {
#pragma unroll
                for (int j = 0; j < 4; j++) {
                    const int p = j >> 1, q = j & 1;
                    mma16816(acc[i][j], ah[i], bh[p][q], bh[p][q + 2]);
                    mma16816(acc[i][j], ah[i], bl[p][q], bl[p][q + 2]);
                    mma16816(acc[i][j], al[i], bh[p][q], bh[p][q + 2]);
                }
            }
        }
    }

    const int r_base = lane >> 2;
    const int c_base = (lane & 3) * 2;
#pragma unroll
    for (int i = 0; i < 4; i++) {
#pragma unroll
        for (int j = 0; j < 4; j++) {
            int col = j0 + warp_n + j * 8 + c_base;
            int h = col >> 6, c = col & 63;
            int n1 = n0 + warp_m + i * 16 + r_base;
            int b1 = n1 >> 11, s1 = n1 & (SS - 1);
            int n2 = n1 + 8;
            int b2 = n2 >> 11, s2 = n2 & (SS - 1);
            size_t o1 = (((size_t)(b1 * HH + h) * SS + s1) * HD) + c;
            size_t o2 = (((size_t)(b2 * HH + h) * SS + s2) * HD) + c;
            if (z == 2) {
                *(float2*)&g_V[o1] = make_float2(acc[i][j][0], acc[i][j][1]);
                *(float2*)&g_V[o2] = make_float2(acc[i][j][2], acc[i][j][3]);
            } else {
                __nv_bfloat16* Oh = (z == 0) ? g_Qhi : g_Khi;
                __nv_bfloat16* Ol = (z == 0) ? g_Qlo : g_Klo;
                uint32_t h1, l1, h2, l2;
                split_pack(acc[i][j][0], acc[i][j][1], h1, l1);
                split_pack(acc[i][j][2], acc[i][j][3], h2, l2);
                *(uint32_t*)&Oh[o1] = h1;
                *(uint32_t*)&Ol[o1] = l1;
                *(uint32_t*)&Oh[o2] = h2;
                *(uint32_t*)&Ol[o2] = l2;
            }
        }
    }
}

// ---------------------------------------------------------------------------
// V transpose: g_V fp32 [bh][s][64] -> g_Vthi/lo bf16 [bh][c][s]
// ---------------------------------------------------------------------------
__global__ __launch_bounds__(256) void v_transpose_kernel()
{
    __shared__ float t[32][33];
    const int tx = threadIdx.x, ty = threadIdx.y;
    const int s0 = blockIdx.x * 32;
    const int c0 = blockIdx.y * 32;
    const int bh = blockIdx.z;
    const float* src = g_V + (size_t)bh * SS * HD;
#pragma unroll
    for (int j = 0; j < 4; j++)
        t[ty + j * 8][tx] = src[(size_t)(s0 + ty + j * 8) * HD + c0 + tx];
    __syncthreads();
#pragma unroll
    for (int j = 0; j < 4; j++) {
        int c = c0 + ty + j * 8;
        int s = s0 + tx;
        float v = t[tx][ty + j * 8];
        __nv_bfloat16 h = __float2bfloat16(v);
        __nv_bfloat16 l = __float2bfloat16(v - __bfloat162float(h));
        size_t o = (size_t)bh * HD * SS + (size_t)c * SS + s;
        g_Vthi[o] = h;
        g_Vtlo[o] = l;
    }
}

// ---------------------------------------------------------------------------
// Flash attention on mma.sync. Block = (bh, 128 q rows), 8 warps x 16 rows.
// BK=64 per iteration. Split-bf16 for QK^T and PV (3 MMAs each).
// Flash tiles: rows of 64 bf16 = 128 B data, stride FRSB = 144 B (16 B pad).
// SMEM plan (36864 B, phase-overlapped):
//   Q-stage phase : Qhi @ 0        (128 rows), Qlo @ 18432 (128 rows)
//   mainloop phase: Kh @ 0, Kl @ 9216, Vh @ 18432, Vl @ 27648 (64 rows each)
// ---------------------------------------------------------------------------
#define FRSB 144

__global__ __launch_bounds__(256) void flash_mma_kernel(
    const float* __restrict__ mask, float* __restrict__ out)
{
    __shared__ __align__(16) unsigned char sm[4 * 64 * FRSB];   // 36864 B
    __shared__ float smask[64];

    const int tid = threadIdx.x;
    const int warp = tid >> 5, lane = tid & 31;
    const int q0 = blockIdx.x * 128;
    const int bh = blockIdx.y;
    const int b = bh >> 4, h = bh & 15;

    const uint32_t uS  = smem_u32(sm);
    const uint32_t uKh = uS;
    const uint32_t uKl = uS + 9216;
    const uint32_t uVh = uS + 18432;
    const uint32_t uVl = uS + 27648;

    const char* Qhp  = (const char*)g_Qhi  + (size_t)bh * SS * HD * 2 + (size_t)q0 * 128;
    const char* Qlp  = (const char*)g_Qlo  + (size_t)bh * SS * HD * 2 + (size_t)q0 * 128;
    const char* Khp  = (const char*)g_Khi  + (size_t)bh * SS * HD * 2;
    const char* Klp  = (const char*)g_Klo  + (size_t)bh * SS * HD * 2;
    const char* Vthp = (const char*)g_Vthi + (size_t)bh * HD * SS * 2;
    const char* Vtlp = (const char*)g_Vtlo + (size_t)bh * HD * SS * 2;
    const float* maskb = mask + b * SS;

    // ---- stage Q tile (128 rows x 128 B, hi @ 0 / lo @ 18432) ----
#pragma unroll
    for (int u = 0; u < 4; u++) {
        int id = u * 256 + tid;
        int row = id >> 3;
        int qb  = (id & 7) * 16;
        size_t go = (size_t)row * 128 + qb;
        *(uint4*)(sm + row * FRSB + qb)         = *(const uint4*)(Qhp + go);
        *(uint4*)(sm + 18432 + row * FRSB + qb) = *(const uint4*)(Qlp + go);
    }
    __syncthreads();
    uint32_t qh[4][4], ql[4][4];
    {
        uint32_t arow = warp * 16 + (lane & 15);
        uint32_t acol = (lane >> 4) * 16;
#pragma unroll
        for (int t = 0; t < 4; t++) {
            uint32_t off = arow * FRSB + t * 32 + acol;
            ldm_x4(qh[t], uS + off);
            ldm_x4(ql[t], uS + 18432 + off);
        }
    }

    const uint32_t brow = (lane & 7) + ((lane >> 3) & 1) * 8;
    const uint32_t bcol = (lane >> 4) * 16;
    const int qq = lane & 3;

    float oacc[8][4] = {};
    float m0 = -1e30f, m1 = -1e30f, l0 = 0.f, l1 = 0.f;

    for (int kt = 0; kt < SS; kt += 64) {
        __syncthreads();
        // ---- cooperative tile loads: K hi/lo [64][64], Vt hi/lo [64][64] ----
#pragma unroll
        for (int u = 0; u < 2; u++) {
            int id = u * 256 + tid;
            int row = id >> 3;
            int qb  = (id & 7) * 16;
            uint32_t so = row * FRSB + qb;
            size_t gK = (size_t)(kt + row) * 128 + qb;
            size_t gV = (size_t)row * (SS * 2) + (size_t)kt * 2 + qb;
            *(uint4*)(sm + so)         = *(const uint4*)(Khp + gK);
            *(uint4*)(sm + 9216 + so)  = *(const uint4*)(Klp + gK);
            *(uint4*)(sm + 18432 + so) = *(const uint4*)(Vthp + gV);
            *(uint4*)(sm + 27648 + so) = *(const uint4*)(Vtlp + gV);
        }
        if (tid < 64) smask[tid] = maskb[kt + tid] * -1e9f;
        __syncthreads();

        // ---- scores S[16x64] per warp ----
        float sacc[8][4] = {};
#pragma unroll
        for (int t = 0; t < 4; t++) {
            const uint32_t koff = t * 32;
#pragma unroll
            for (int g = 0; g < 4; g++) {
                uint32_t bh_[4], bl_[4];
                uint32_t off = (g * 16 + brow) * FRSB + koff + bcol;
                ldm_x4(bh_, uKh + off);
                ldm_x4(bl_, uKl + off);
#pragma unroll
                for (int q = 0; q < 2; q++) {
                    const int n = 2 * g + q;
                    mma16816(sacc[n], qh[t], bh_[q], bh_[q + 2]);
                    mma16816(sacc[n], qh[t], bl_[q], bl_[q + 2]);
                    mma16816(sacc[n], ql[t], bh_[q], bh_[q + 2]);
                }
            }
        }

        // ---- online softmax on fragments ----
        float mx0 = -1e30f, mx1 = -1e30f;
#pragma unroll
        for (int n = 0; n < 8; n++) {
            float mv0 = smask[8 * n + 2 * qq];
            float mv1 = smask[8 * n + 2 * qq + 1];
            sacc[n][0] = sacc[n][0] * 0.125f + mv0;
            sacc[n][1] = sacc[n][1] * 0.125f + mv1;
            sacc[n][2] = sacc[n][2] * 0.125f + mv0;
            sacc[n][3] = sacc[n][3] * 0.125f + mv1;
            mx0 = fmaxf(mx0, fmaxf(sacc[n][0], sacc[n][1]));
            mx1 = fmaxf(mx1, fmaxf(sacc[n][2], sacc[n][3]));
        }
        mx0 = fmaxf(mx0, __shfl_xor_sync(0xffffffffu, mx0, 1));
        mx0 = fmaxf(mx0, __shfl_xor_sync(0xffffffffu, mx0, 2));
        mx1 = fmaxf(mx1, __shfl_xor_sync(0xffffffffu, mx1, 1));
        mx1 = fmaxf(mx1, __shfl_xor_sync(0xffffffffu, mx1, 2));
        float mn0 = fmaxf(m0, mx0), mn1 = fmaxf(m1, mx1);
        float a0 = __expf(m0 - mn0), a1 = __expf(m1 - mn1);
        m0 = mn0; m1 = mn1;

        float rs0 = 0.f, rs1 = 0.f;
#pragma unroll
        for (int n = 0; n < 8; n++) {
            sacc[n][0] = __expf(sacc[n][0] - mn0);
            sacc[n][1] = __expf(sacc[n][1] - mn0);
            sacc[n][2] = __expf(sacc[n][2] - mn1);
            sacc[n][3] = __expf(sacc[n][3] - mn1);
            rs0 += sacc[n][0] + sacc[n][1];
            rs1 += sacc[n][2] + sacc[n][3];
        }
        rs0 += __shfl_xor_sync(0xffffffffu, rs0, 1);
        rs0 += __shfl_xor_sync(0xffffffffu, rs0, 2);
        rs1 += __shfl_xor_sync(0xffffffffu, rs1, 1);
        rs1 += __shfl_xor_sync(0xffffffffu, rs1, 2);
        l0 = l0 * a0 + rs0;
        l1 = l1 * a1 + rs1;
#pragma unroll
        for (int n = 0; n < 8; n++) {
            oacc[n][0] *= a0;
            oacc[n][1] *= a0;
            oacc[n][2] *= a1;
            oacc[n][3] *= a1;
        }

        // ---- O += P * Vt  (P fragments reused in-register as A fragments) ----
#pragma unroll
        for (int t = 0; t < 4; t++) {
            uint32_t Ah[4], Al[4];
            split_pack(sacc[2 * t][0],     sacc[2 * t][1],     Ah[0], Al[0]);
            split_pack(sacc[2 * t][2],     sacc[2 * t][3],     Ah[1], Al[1]);
            split_pack(sacc[2 * t + 1][0], sacc[2 * t + 1][1], Ah[2], Al[2]);
            split_pack(sacc[2 * t + 1][2], sacc[2 * t + 1][3], Ah[3], Al[3]);
            const uint32_t koff = t * 32;
#pragma unroll
            for (int g = 0; g < 4; g++) {
                uint32_t vh_[4], vl_[4];
                uint32_t off = (g * 16 + brow) * FRSB + koff + bcol;
                ldm_x4(vh_, uVh + off);
                ldm_x4(vl_, uVl + off);
#pragma unroll
                for (int q = 0; q < 2; q++) {
                    const int n = 2 * g + q;
                    mma16816(oacc[n], Ah, vh_[q], vh_[q + 2]);
                    mma16816(oacc[n], Ah, vl_[q], vl_[q + 2]);
                    mma16816(oacc[n], Al, vh_[q], vh_[q + 2]);
                }
            }
        }
    }

    // ---- epilogue: normalize, write out[b][s][h*64+c] ----
    float inv0 = 1.0f / l0, inv1 = 1.0f / l1;
    int s0 = q0 + warp * 16 + (lane >> 2);
    int s1 = s0 + 8;
#pragma unroll
    for (int n = 0; n < 8; n++) {
        int col = h * HD + 8 * n + 2 * qq;
        *(float2*)&out[(size_t)(b * SS + s0) * DD + col] =
            make_float2(oacc[n][0] * inv0, oacc[n][1] * inv0);
        *(float2*)&out[(size_t)(b * SS + s1) * DD + col] =
            make_float2(oacc[n][2] * inv1, oacc[n][3] * inv1);
    }
}

// ---------------------------------------------------------------------------
extern "C" void kernel_launch(void* const* d_in, const int* in_sizes, int n_in,
                              void* d_out, int out_size)
{
    const float* X    = (const float*)d_in[0];
    const float* mask = (const float*)d_in[1];
    const float* wq   = (const float*)d_in[2];
    const float* wk   = (const float*)d_in[3];
    const float* wv   = (const float*)d_in[4];
    float* out = (float*)d_out;

    convert_x_kernel<<<(BB * SS * DD) / 4 / 256, 256>>>(X);
    convert_w_kernel<<<dim3(DD / 32, DD / 32, 3), dim3(32, 8)>>>(wq, wk, wv);
    qkv_mma_kernel<<<dim3(DD / 128, (BB * SS) / 128, 3), 256>>>();
    v_transpose_kernel<<<dim3(SS / 32, HD / 32, BB * HH), dim3(32, 8)>>>();
    flash_mma_kernel<<<dim3(SS / 128, BB * HH), 256>>>(mask, out);
}

// round 10
// speedup vs baseline: 2.7654x; 1.1340x over previous
#include <cuda_runtime.h>
#include <cuda_bf16.h>
#include <cstdint>

#define BB 2
#define SS 2048
#define DD 1024
#define HH 16
#define HD 64

// ---------------------------------------------------------------------------
// Global scratch (allocation-free per harness rules)
// ---------------------------------------------------------------------------
__device__ float g_V[BB * HH * SS * HD];                 // fp32 V (transpose source)

__device__ __nv_bfloat16 g_Qhi[BB * HH * SS * HD];
__device__ __nv_bfloat16 g_Qlo[BB * HH * SS * HD];
__device__ __nv_bfloat16 g_Khi[BB * HH * SS * HD];
__device__ __nv_bfloat16 g_Klo[BB * HH * SS * HD];
__device__ __nv_bfloat16 g_Vthi[BB * HH * HD * SS];      // [bh][c][s]
__device__ __nv_bfloat16 g_Vtlo[BB * HH * HD * SS];

__device__ __nv_bfloat16 g_Xhi[BB * SS * DD];
__device__ __nv_bfloat16 g_Xlo[BB * SS * DD];
__device__ __nv_bfloat16 g_Whi[3 * DD * DD];             // transposed: [mat][n][k]
__device__ __nv_bfloat16 g_Wlo[3 * DD * DD];

// ---------------------------------------------------------------------------
// Warp-MMA + cp.async helpers
// ---------------------------------------------------------------------------
__device__ __forceinline__ uint32_t smem_u32(const void* p) {
    uint32_t a;
    asm("{ .reg .u64 t; cvta.to.shared.u64 t, %1; cvt.u32.u64 %0, t; }" : "=r"(a) : "l"(p));
    return a;
}
__device__ __forceinline__ void ldm_x4(uint32_t* r, uint32_t addr) {
    asm volatile("ldmatrix.sync.aligned.m8n8.x4.shared.b16 {%0,%1,%2,%3}, [%4];"
                 : "=r"(r[0]), "=r"(r[1]), "=r"(r[2]), "=r"(r[3]) : "r"(addr));
}
__device__ __forceinline__ void mma16816(float* c, const uint32_t* a, uint32_t b0, uint32_t b1) {
    asm volatile(
        "mma.sync.aligned.m16n8k16.row.col.f32.bf16.bf16.f32 "
        "{%0,%1,%2,%3}, {%4,%5,%6,%7}, {%8,%9}, {%0,%1,%2,%3};"
        : "+f"(c[0]), "+f"(c[1]), "+f"(c[2]), "+f"(c[3])
        : "r"(a[0]), "r"(a[1]), "r"(a[2]), "r"(a[3]), "r"(b0), "r"(b1));
}
__device__ __forceinline__ void split_pack(float a, float b, uint32_t& hi, uint32_t& lo) {
    __nv_bfloat16 ha = __float2bfloat16(a), hb = __float2bfloat16(b);
    __nv_bfloat16 la = __float2bfloat16(a - __bfloat162float(ha));
    __nv_bfloat16 lb = __float2bfloat16(b - __bfloat162float(hb));
    __nv_bfloat162 h2(ha, hb), l2(la, lb);
    hi = *(uint32_t*)&h2;
    lo = *(uint32_t*)&l2;
}
__device__ __forceinline__ void cp16(uint32_t dst, const void* src) {
    asm volatile("cp.async.cg.shared.global [%0], [%1], 16;" :: "r"(dst), "l"(src));
}
#define CP_COMMIT() asm volatile("cp.async.commit_group;" ::: "memory")
#define CP_WAIT0()  asm volatile("cp.async.wait_group 0;"  ::: "memory")

// ---------------------------------------------------------------------------
// Prep: split X into bf16 hi/lo
// ---------------------------------------------------------------------------
__global__ __launch_bounds__(256) void convert_x_kernel(const float* __restrict__ X)
{
    int idx = blockIdx.x * 256 + threadIdx.x;
    float4 v = ((const float4*)X)[idx];
    float f[4] = {v.x, v.y, v.z, v.w};
    __nv_bfloat16 h[4], l[4];
#pragma unroll
    for (int i = 0; i < 4; i++) {
        h[i] = __float2bfloat16(f[i]);
        l[i] = __float2bfloat16(f[i] - __bfloat162float(h[i]));
    }
    __nv_bfloat162* dh = (__nv_bfloat162*)g_Xhi;
    __nv_bfloat162* dl = (__nv_bfloat162*)g_Xlo;
    dh[idx * 2 + 0] = __nv_bfloat162(h[0], h[1]);
    dh[idx * 2 + 1] = __nv_bfloat162(h[2], h[3]);
    dl[idx * 2 + 0] = __nv_bfloat162(l[0], l[1]);
    dl[idx * 2 + 1] = __nv_bfloat162(l[2], l[3]);
}

// ---------------------------------------------------------------------------
// Prep: transpose W [k][n] -> Wt [n][k], split bf16 hi/lo
// ---------------------------------------------------------------------------
__global__ __launch_bounds__(256) void convert_w_kernel(
    const float* __restrict__ wq, const float* __restrict__ wk, const float* __restrict__ wv)
{
    __shared__ float t[32][33];
    const int z = blockIdx.z;
    const float* W = (z == 0) ? wq : ((z == 1) ? wk : wv);
    const int tx = threadIdx.x, ty = threadIdx.y;
    const int n_in = blockIdx.x * 32 + tx;
#pragma unroll
    for (int j = 0; j < 4; j++) {
        int k = blockIdx.y * 32 + ty + j * 8;
        t[ty + j * 8][tx] = W[k * DD + n_in];
    }
    __syncthreads();
#pragma unroll
    for (int j = 0; j < 4; j++) {
        int n = blockIdx.x * 32 + ty + j * 8;
        int k = blockIdx.y * 32 + tx;
        float v = t[tx][ty + j * 8];
        __nv_bfloat16 h = __float2bfloat16(v);
        __nv_bfloat16 l = __float2bfloat16(v - __bfloat162float(h));
        size_t o = (size_t)z * DD * DD + (size_t)n * DD + k;
        g_Whi[o] = h;
        g_Wlo[o] = l;
    }
}

// ---------------------------------------------------------------------------
// mma.sync QKV GEMM, cp.async double-buffered.
// Rows 32 bf16 = 64 B data, stride 80 B. Stage = 4 buffers x 10240 B = 40960 B.
// Dynamic smem: 2 stages = 81920 B.
// ---------------------------------------------------------------------------
#define RSB 80
#define QSTG 40960

__global__ __launch_bounds__(256) void qkv_mma_kernel()
{
    extern __shared__ __align__(16) unsigned char dsm[];

    const int tid  = threadIdx.x;
    const int warp = tid >> 5, lane = tid & 31;
    const int warp_m = (warp & 1) * 64;
    const int warp_n = (warp >> 1) * 32;
    const int j0 = blockIdx.x * 128;
    const int n0 = blockIdx.y * 128;
    const int z  = blockIdx.z;

    const char* Ahp = (const char*)g_Xhi + (size_t)n0 * (DD * 2);
    const char* Alp = (const char*)g_Xlo + (size_t)n0 * (DD * 2);
    const char* Bhp = (const char*)g_Whi + ((size_t)z * DD * DD + (size_t)j0 * DD) * 2;
    const char* Blp = (const char*)g_Wlo + ((size_t)z * DD * DD + (size_t)j0 * DD) * 2;

    const uint32_t base = smem_u32(dsm);

    // per-thread load coords (2 uint4 per buffer per chunk)
    const int lrow0 = tid >> 2;            // rows 0..63
    const int lqb   = (tid & 3) * 16;

    float acc[4][4][4] = {};

    const uint32_t a_row = warp_m + (lane & 15);
    const uint32_t a_col = (lane >> 4) * 16;
    const uint32_t b_row = warp_n + (lane & 7) + ((lane >> 3) & 1) * 8;
    const uint32_t b_col = (lane >> 4) * 16;

    // prefetch chunk 0 -> stage 0
    {
#pragma unroll
        for (int u = 0; u < 2; u++) {
            int row = lrow0 + u * 64;
            size_t go = (size_t)row * (DD * 2) + lqb;
            uint32_t so = row * RSB + lqb;
            cp16(base + so,         Ahp + go);
            cp16(base + so + 10240, Alp + go);
            cp16(base + so + 20480, Bhp + go);
            cp16(base + so + 30720, Blp + go);
        }
        CP_COMMIT();
    }

    for (int kc = 0; kc < 32; kc++) {
        CP_WAIT0();
        __syncthreads();
        if (kc + 1 < 32) {
            const size_t kb = (size_t)(kc + 1) * 64;
            const uint32_t sb = ((kc + 1) & 1) * QSTG;
#pragma unroll
            for (int u = 0; u < 2; u++) {
                int row = lrow0 + u * 64;
                size_t go = (size_t)row * (DD * 2) + kb + lqb;
                uint32_t so = sb + row * RSB + lqb;
                cp16(base + so,         Ahp + go);
                cp16(base + so + 10240, Alp + go);
                cp16(base + so + 20480, Bhp + go);
                cp16(base + so + 30720, Blp + go);
            }
            CP_COMMIT();
        }

        const uint32_t sb = (kc & 1) * QSTG;
        const uint32_t uAh = base + sb, uAl = base + sb + 10240;
        const uint32_t uBh = base + sb + 20480, uBl = base + sb + 30720;
#pragma unroll
        for (int ks = 0; ks < 2; ks++) {
            const uint32_t koff = ks * 32;
            uint32_t ah[4][4], al[4][4];
#pragma unroll
            for (int i = 0; i < 4; i++) {
                uint32_t off = (a_row + i * 16) * RSB + koff + a_col;
                ldm_x4(ah[i], uAh + off);
                ldm_x4(al[i], uAl + off);
            }
            uint32_t bh[2][4], bl[2][4];
#pragma unroll
            for (int p = 0; p < 2; p++) {
                uint32_t off = (b_row + p * 16) * RSB + koff + b_col;
                ldm_x4(bh[p], uBh + off);
                ldm_x4(bl[p], uBl + off);
            }
#pragma unroll
            for (int i = 0; i < 4; i++) {
#pragma unroll
                for (int j = 0; j < 4; j++) {
                    const int p = j >> 1, q = j & 1;
                    mma16816(acc[i][j], ah[i], bh[p][q], bh[p][q + 2]);
                    mma16816(acc[i][j], ah[i], bl[p][q], bl[p][q + 2]);
                    mma16816(acc[i][j], al[i], bh[p][q], bh[p][q + 2]);
                }
            }
        }
    }

    const int r_base = lane >> 2;
    const int c_base = (lane & 3) * 2;
#pragma unroll
    for (int i = 0; i < 4; i++) {
#pragma unroll
        for (int j = 0; j < 4; j++) {
            int col = j0 + warp_n + j * 8 + c_base;
            int h = col >> 6, c = col & 63;
            int n1 = n0 + warp_m + i * 16 + r_base;
            int b1 = n1 >> 11, s1 = n1 & (SS - 1);
            int n2 = n1 + 8;
            int b2 = n2 >> 11, s2 = n2 & (SS - 1);
            size_t o1 = (((size_t)(b1 * HH + h) * SS + s1) * HD) + c;
            size_t o2 = (((size_t)(b2 * HH + h) * SS + s2) * HD) + c;
            if (z == 2) {
                *(float2*)&g_V[o1] = make_float2(acc[i][j][0], acc[i][j][1]);
                *(float2*)&g_V[o2] = make_float2(acc[i][j][2], acc[i][j][3]);
            } else {
                __nv_bfloat16* Oh = (z == 0) ? g_Qhi : g_Khi;
                __nv_bfloat16* Ol = (z == 0) ? g_Qlo : g_Klo;
                uint32_t h1, l1, h2, l2;
                split_pack(acc[i][j][0], acc[i][j][1], h1, l1);
                split_pack(acc[i][j][2], acc[i][j][3], h2, l2);
                *(uint32_t*)&Oh[o1] = h1;
                *(uint32_t*)&Ol[o1] = l1;
                *(uint32_t*)&Oh[o2] = h2;
                *(uint32_t*)&Ol[o2] = l2;
            }
        }
    }
}

// ---------------------------------------------------------------------------
// V transpose: g_V fp32 [bh][s][64] -> g_Vthi/lo bf16 [bh][c][s]
// ---------------------------------------------------------------------------
__global__ __launch_bounds__(256) void v_transpose_kernel()
{
    __shared__ float t[32][33];
    const int tx = threadIdx.x, ty = threadIdx.y;
    const int s0 = blockIdx.x * 32;
    const int c0 = blockIdx.y * 32;
    const int bh = blockIdx.z;
    const float* src = g_V + (size_t)bh * SS * HD;
#pragma unroll
    for (int j = 0; j < 4; j++)
        t[ty + j * 8][tx] = src[(size_t)(s0 + ty + j * 8) * HD + c0 + tx];
    __syncthreads();
#pragma unroll
    for (int j = 0; j < 4; j++) {
        int c = c0 + ty + j * 8;
        int s = s0 + tx;
        float v = t[tx][ty + j * 8];
        __nv_bfloat16 h = __float2bfloat16(v);
        __nv_bfloat16 l = __float2bfloat16(v - __bfloat162float(h));
        size_t o = (size_t)bh * HD * SS + (size_t)c * SS + s;
        g_Vthi[o] = h;
        g_Vtlo[o] = l;
    }
}

// ---------------------------------------------------------------------------
// Flash attention, cp.async double-buffered (K/V tiles only; mask via plain
// LDG->STS with -1e9 premultiply, restoring round-7 semantics).
// Tile rows 64 bf16 = 128 B data, stride FRSB = 144 B.
// Stage = Kh|Kl|Vh|Vl, 4 x 9216 B = 36864 B; 2 stages = 73728 B dynamic.
// Q staged into stage-1 region before the mainloop (consumed to registers).
// ---------------------------------------------------------------------------
#define FRSB 144
#define FSTG 36864

__global__ __launch_bounds__(256) void flash_mma_kernel(
    const float* __restrict__ mask, float* __restrict__ out)
{
    extern __shared__ __align__(16) unsigned char dsm[];
    __shared__ __align__(16) float smask2[2][64];

    const int tid = threadIdx.x;
    const int warp = tid >> 5, lane = tid & 31;
    const int q0 = blockIdx.x * 128;
    const int bh = blockIdx.y;
    const int b = bh >> 4, h = bh & 15;

    const uint32_t base = smem_u32(dsm);

    const char* Qhp  = (const char*)g_Qhi  + (size_t)bh * SS * HD * 2 + (size_t)q0 * 128;
    const char* Qlp  = (const char*)g_Qlo  + (size_t)bh * SS * HD * 2 + (size_t)q0 * 128;
    const char* Khp  = (const char*)g_Khi  + (size_t)bh * SS * HD * 2;
    const char* Klp  = (const char*)g_Klo  + (size_t)bh * SS * HD * 2;
    const char* Vthp = (const char*)g_Vthi + (size_t)bh * HD * SS * 2;
    const char* Vtlp = (const char*)g_Vtlo + (size_t)bh * HD * SS * 2;
    const float* maskb = mask + b * SS;

    // per-thread K/V tile load coords (2 uint4 per buffer per tile)
    const int frow0 = tid >> 3;            // rows 0..31
    const int fqb   = (tid & 7) * 16;

    // ---- prefetch K/V tile 0 -> stage 0 (overlaps Q staging) ----
    {
#pragma unroll
        for (int u = 0; u < 2; u++) {
            int row = frow0 + u * 32;
            uint32_t so = row * FRSB + fqb;
            size_t gK = (size_t)row * 128 + fqb;
            size_t gV = (size_t)row * (SS * 2) + fqb;
            cp16(base + so,         Khp + gK);
            cp16(base + so + 9216,  Klp + gK);
            cp16(base + so + 18432, Vthp + gV);
            cp16(base + so + 27648, Vtlp + gV);
        }
        CP_COMMIT();
    }
    if (tid < 64) smask2[0][tid] = maskb[tid] * -1e9f;

    // ---- stage Q tile (128 rows x 128 B) into stage-1 region ----
#pragma unroll
    for (int u = 0; u < 4; u++) {
        int id = u * 256 + tid;
        int row = id >> 3;
        int qb  = (id & 7) * 16;
        size_t go = (size_t)row * 128 + qb;
        *(uint4*)(dsm + FSTG + row * FRSB + qb)         = *(const uint4*)(Qhp + go);
        *(uint4*)(dsm + FSTG + 18432 + row * FRSB + qb) = *(const uint4*)(Qlp + go);
    }
    __syncthreads();
    uint32_t qh[4][4], ql[4][4];
    {
        uint32_t arow = warp * 16 + (lane & 15);
        uint32_t acol = (lane >> 4) * 16;
#pragma unroll
        for (int t = 0; t < 4; t++) {
            uint32_t off = arow * FRSB + t * 32 + acol;
            ldm_x4(qh[t], base + FSTG + off);
            ldm_x4(ql[t], base + FSTG + 18432 + off);
        }
    }

    const uint32_t brow = (lane & 7) + ((lane >> 3) & 1) * 8;
    const uint32_t bcol = (lane >> 4) * 16;
    const int qq = lane & 3;

    float oacc[8][4] = {};
    float m0 = -1e30f, m1 = -1e30f, l0 = 0.f, l1 = 0.f;

    for (int it = 0; it < 32; it++) {
        CP_WAIT0();
        __syncthreads();   // tile `it` landed; all threads done with stage (it-2) & Q frags
        if (it + 1 < 32) {
            const int ktn = (it + 1) * 64;
            const uint32_t sb = ((it + 1) & 1) * FSTG;
#pragma unroll
            for (int u = 0; u < 2; u++) {
                int row = frow0 + u * 32;
                uint32_t so = sb + row * FRSB + fqb;
                size_t gK = (size_t)(ktn + row) * 128 + fqb;
                size_t gV = (size_t)row * (SS * 2) + (size_t)ktn * 2 + fqb;
                cp16(base + so,         Khp + gK);
                cp16(base + so + 9216,  Klp + gK);
                cp16(base + so + 18432, Vthp + gV);
                cp16(base + so + 27648, Vtlp + gV);
            }
            CP_COMMIT();
            if (tid < 64) smask2[(it + 1) & 1][tid] = maskb[ktn + tid] * -1e9f;
        }

        const int stg = it & 1;
        const uint32_t uKh = base + stg * FSTG;
        const uint32_t uKl = uKh + 9216;
        const uint32_t uVh = uKh + 18432;
        const uint32_t uVl = uKh + 27648;
        const float* smask = smask2[stg];

        // ---- scores S[16x64] per warp ----
        float sacc[8][4] = {};
#pragma unroll
        for (int t = 0; t < 4; t++) {
            const uint32_t koff = t * 32;
#pragma unroll
            for (int g = 0; g < 4; g++) {
                uint32_t bh_[4], bl_[4];
                uint32_t off = (g * 16 + brow) * FRSB + koff + bcol;
                ldm_x4(bh_, uKh + off);
                ldm_x4(bl_, uKl + off);
#pragma unroll
                for (int q = 0; q < 2; q++) {
                    const int n = 2 * g + q;
                    mma16816(sacc[n], qh[t], bh_[q], bh_[q + 2]);
                    mma16816(sacc[n], qh[t], bl_[q], bl_[q + 2]);
                    mma16816(sacc[n], ql[t], bh_[q], bh_[q + 2]);
                }
            }
        }

        // ---- online softmax on fragments ----
        float mx0 = -1e30f, mx1 = -1e30f;
#pragma unroll
        for (int n = 0; n < 8; n++) {
            float mv0 = smask[8 * n + 2 * qq];
            float mv1 = smask[8 * n + 2 * qq + 1];
            sacc[n][0] = sacc[n][0] * 0.125f + mv0;
            sacc[n][1] = sacc[n][1] * 0.125f + mv1;
            sacc[n][2] = sacc[n][2] * 0.125f + mv0;
            sacc[n][3] = sacc[n][3] * 0.125f + mv1;
            mx0 = fmaxf(mx0, fmaxf(sacc[n][0], sacc[n][1]));
            mx1 = fmaxf(mx1, fmaxf(sacc[n][2], sacc[n][3]));
        }
        mx0 = fmaxf(mx0, __shfl_xor_sync(0xffffffffu, mx0, 1));
        mx0 = fmaxf(mx0, __shfl_xor_sync(0xffffffffu, mx0, 2));
        mx1 = fmaxf(mx1, __shfl_xor_sync(0xffffffffu, mx1, 1));
        mx1 = fmaxf(mx1, __shfl_xor_sync(0xffffffffu, mx1, 2));
        float mn0 = fmaxf(m0, mx0), mn1 = fmaxf(m1, mx1);
        float a0 = __expf(m0 - mn0), a1 = __expf(m1 - mn1);
        m0 = mn0; m1 = mn1;

        float rs0 = 0.f, rs1 = 0.f;
#pragma unroll
        for (int n = 0; n < 8; n++) {
            sacc[n][0] = __expf(sacc[n][0] - mn0);
            sacc[n][1] = __expf(sacc[n][1] - mn0);
            sacc[n][2] = __expf(sacc[n][2] - mn1);
            sacc[n][3] = __expf(sacc[n][3] - mn1);
            rs0 += sacc[n][0] + sacc[n][1];
            rs1 += sacc[n][2] + sacc[n][3];
        }
        rs0 += __shfl_xor_sync(0xffffffffu, rs0, 1);
        rs0 += __shfl_xor_sync(0xffffffffu, rs0, 2);
        rs1 += __shfl_xor_sync(0xffffffffu, rs1, 1);
        rs1 += __shfl_xor_sync(0xffffffffu, rs1, 2);
        l0 = l0 * a0 + rs0;
        l1 = l1 * a1 + rs1;
#pragma unroll
        for (int n = 0; n < 8; n++) {
            oacc[n][0] *= a0;
            oacc[n][1] *= a0;
            oacc[n][2] *= a1;
            oacc[n][3] *= a1;
        }

        // ---- O += P * Vt (P fragments reused in-register as A fragments) ----
#pragma unroll
        for (int t = 0; t < 4; t++) {
            uint32_t Ah[4], Al[4];
            split_pack(sacc[2 * t][0],     sacc[2 * t][1],     Ah[0], Al[0]);
            split_pack(sacc[2 * t][2],     sacc[2 * t][3],     Ah[1], Al[1]);
            split_pack(sacc[2 * t + 1][0], sacc[2 * t + 1][1], Ah[2], Al[2]);
            split_pack(sacc[2 * t + 1][2], sacc[2 * t + 1][3], Ah[3], Al[3]);
            const uint32_t koff = t * 32;
#pragma unroll
            for (int g = 0; g < 4; g++) {
                uint32_t vh_[4], vl_[4];
                uint32_t off = (g * 16 + brow) * FRSB + koff + bcol;
                ldm_x4(vh_, uVh + off);
                ldm_x4(vl_, uVl + off);
#pragma unroll
                for (int q = 0; q < 2; q++) {
                    const int n = 2 * g + q;
                    mma16816(oacc[n], Ah, vh_[q], vh_[q + 2]);
                    mma16816(oacc[n], Ah, vl_[q], vl_[q + 2]);
                    mma16816(oacc[n], Al, vh_[q], vh_[q + 2]);
                }
            }
        }
    }

    // ---- epilogue: normalize, write out[b][s][h*64+c] ----
    float inv0 = 1.0f / l0, inv1 = 1.0f / l1;
    int s0 = q0 + warp * 16 + (lane >> 2);
    int s1 = s0 + 8;
#pragma unroll
    for (int n = 0; n < 8; n++) {
        int col = h * HD + 8 * n + 2 * qq;
        *(float2*)&out[(size_t)(b * SS + s0) * DD + col] =
            make_float2(oacc[n][0] * inv0, oacc[n][1] * inv0);
        *(float2*)&out[(size_t)(b * SS + s1) * DD + col] =
            make_float2(oacc[n][2] * inv1, oacc[n][3] * inv1);
    }
}

// ---------------------------------------------------------------------------
extern "C" void kernel_launch(void* const* d_in, const int* in_sizes, int n_in,
                              void* d_out, int out_size)
{
    const float* X    = (const float*)d_in[0];
    const float* mask = (const float*)d_in[1];
    const float* wq   = (const float*)d_in[2];
    const float* wk   = (const float*)d_in[3];
    const float* wv   = (const float*)d_in[4];
    float* out = (float*)d_out;

    cudaFuncSetAttribute(qkv_mma_kernel,  cudaFuncAttributeMaxDynamicSharedMemorySize, 2 * QSTG);
    cudaFuncSetAttribute(flash_mma_kernel, cudaFuncAttributeMaxDynamicSharedMemorySize, 2 * FSTG);

    convert_x_kernel<<<(BB * SS * DD) / 4 / 256, 256>>>(X);
    convert_w_kernel<<<dim3(DD / 32, DD / 32, 3), dim3(32, 8)>>>(wq, wk, wv);
    qkv_mma_kernel<<<dim3(DD / 128, (BB * SS) / 128, 3), 256, 2 * QSTG>>>();
    v_transpose_kernel<<<dim3(SS / 32, HD / 32, BB * HH), dim3(32, 8)>>>();
    flash_mma_kernel<<<dim3(SS / 128, BB * HH), 256, 2 * FSTG>>>(mask, out);
}